// round 1
// baseline (speedup 1.0000x reference)
#include <cuda_runtime.h>
#include <cuda_bf16.h>

// Problem constants
#define B_  8
#define C_  256
#define K_  21
#define HL  64            // low-res H=W
#define PL  (HL*HL)       // 4096 low-res pixels
#define HH  512           // hi-res H=W
#define PH  (HH*HH)       // 262144 hi-res pixels

// Scratch (device globals; no allocation allowed)
__device__ float g_seg  [B_ * K_ * PL];        // softmax at 64x64       (2.75 MB)
__device__ float g_tmpx [B_ * 3 * HH * HL];    // X-pass adjoint          (3 MB)
__device__ float g_xdown[B_ * 3 * PL];         // adjoint-downsampled x   (393 KB)
__device__ float g_q    [B_ * K_ * 3];         // color centroids

// ---------------------------------------------------------------------------
// Kernel 1: logits = fm . W^T + b, softmax over K, at low res.
// grid (32, 8), block 128. One thread per low-res pixel.
// ---------------------------------------------------------------------------
__global__ __launch_bounds__(128) void k_logits_softmax(
    const float* __restrict__ fm, const float* __restrict__ Wc,
    const float* __restrict__ bc)
{
    __shared__ float sW[K_ * C_];   // 21*256*4 = 21.5 KB
    __shared__ float sb[K_];
    int tid = threadIdx.x;
    for (int i = tid; i < K_ * C_; i += 128) sW[i] = Wc[i];
    if (tid < K_) sb[tid] = bc[tid];
    __syncthreads();

    int b = blockIdx.y;
    int p = blockIdx.x * 128 + tid;          // 0..4095
    const float* fmb = fm + (size_t)b * C_ * PL + p;

    float acc[K_];
#pragma unroll
    for (int k = 0; k < K_; k++) acc[k] = sb[k];

#pragma unroll 4
    for (int c = 0; c < C_; c++) {
        float v = fmb[c * PL];               // coalesced across threads
#pragma unroll
        for (int k = 0; k < K_; k++)
            acc[k] = fmaf(v, sW[k * C_ + c], acc[k]);
    }

    // softmax over K in registers
    float m = acc[0];
#pragma unroll
    for (int k = 1; k < K_; k++) m = fmaxf(m, acc[k]);
    float s = 0.f;
#pragma unroll
    for (int k = 0; k < K_; k++) { acc[k] = __expf(acc[k] - m); s += acc[k]; }
    float inv = 1.0f / s;

    float* segb = g_seg + (size_t)b * K_ * PL + p;
#pragma unroll
    for (int k = 0; k < K_; k++) segb[(size_t)k * PL] = acc[k] * inv;
}

// ---------------------------------------------------------------------------
// Kernel 2a: adjoint of bilinear upsample (align_corners), X direction.
// tmpx[b,c,Y,xl] = sum_X w(X->xl) * x[b,c,Y,X]
// ---------------------------------------------------------------------------
__global__ void k_adj_x(const float* __restrict__ x)
{
    int idx = blockIdx.x * blockDim.x + threadIdx.x;
    if (idx >= B_ * 3 * HH * HL) return;
    int xl = idx & (HL - 1);
    int Y  = (idx >> 6) & (HH - 1);
    int bc = idx >> 15;                       // b*3+c

    const float* row = x + ((size_t)bc * HH + Y) * HH;
    const float scale = 63.0f / 511.0f;
    int Xlo = max(0,  (int)floorf((xl - 1) * (511.0f / 63.0f)));
    int Xhi = min(HH - 1, (int)ceilf((xl + 1) * (511.0f / 63.0f)));

    float s = 0.f;
    for (int X = Xlo; X <= Xhi; X++) {
        float xs = (float)X * scale;
        int   x0 = (int)xs;                   // floor, xs >= 0
        float wx = xs - (float)x0;
        int   x1 = min(x0 + 1, HL - 1);
        float w  = (x0 == xl ? (1.0f - wx) : 0.0f) + (x1 == xl ? wx : 0.0f);
        s = fmaf(w, row[X], s);
    }
    g_tmpx[idx] = s;
}

// ---------------------------------------------------------------------------
// Kernel 2b: adjoint, Y direction: xdown[b,c,yl,xl] = sum_Y w(Y->yl)*tmpx[b,c,Y,xl]
// ---------------------------------------------------------------------------
__global__ void k_adj_y()
{
    int idx = blockIdx.x * blockDim.x + threadIdx.x;
    if (idx >= B_ * 3 * PL) return;
    int xl = idx & (HL - 1);
    int yl = (idx >> 6) & (HL - 1);
    int bc = idx >> 12;

    const float scale = 63.0f / 511.0f;
    int Ylo = max(0,  (int)floorf((yl - 1) * (511.0f / 63.0f)));
    int Yhi = min(HH - 1, (int)ceilf((yl + 1) * (511.0f / 63.0f)));

    const float* col = g_tmpx + (size_t)bc * HH * HL + xl;
    float s = 0.f;
    for (int Y = Ylo; Y <= Yhi; Y++) {
        float ys = (float)Y * scale;
        int   y0 = (int)ys;
        float wy = ys - (float)y0;
        int   y1 = min(y0 + 1, HL - 1);
        float w  = (y0 == yl ? (1.0f - wy) : 0.0f) + (y1 == yl ? wy : 0.0f);
        s = fmaf(w, col[(size_t)Y * HL], s);
    }
    g_xdown[idx] = s;
}

// ---------------------------------------------------------------------------
// Kernel 3: q[b,k,c] = (1/HW) * sum_p seg[b,k,p] * xdown[b,c,p]
// grid = B*K blocks, 128 threads.
// ---------------------------------------------------------------------------
__global__ __launch_bounds__(128) void k_q()
{
    int b = blockIdx.x / K_;
    int k = blockIdx.x % K_;
    const float* seg = g_seg   + ((size_t)b * K_ + k) * PL;
    const float* xd  = g_xdown + (size_t)b * 3 * PL;

    float s0 = 0.f, s1 = 0.f, s2 = 0.f;
    for (int i = threadIdx.x; i < PL; i += 128) {
        float sv = seg[i];
        s0 = fmaf(sv, xd[i],          s0);
        s1 = fmaf(sv, xd[PL + i],     s1);
        s2 = fmaf(sv, xd[2 * PL + i], s2);
    }
#pragma unroll
    for (int off = 16; off > 0; off >>= 1) {
        s0 += __shfl_down_sync(0xffffffffu, s0, off);
        s1 += __shfl_down_sync(0xffffffffu, s1, off);
        s2 += __shfl_down_sync(0xffffffffu, s2, off);
    }
    __shared__ float sm[3][4];
    int w = threadIdx.x >> 5, l = threadIdx.x & 31;
    if (l == 0) { sm[0][w] = s0; sm[1][w] = s1; sm[2][w] = s2; }
    __syncthreads();
    if (threadIdx.x == 0) {
        const float invHW = 1.0f / (float)PH;
        float* qo = g_q + ((size_t)b * K_ + k) * 3;
        qo[0] = (sm[0][0] + sm[0][1] + sm[0][2] + sm[0][3]) * invHW;
        qo[1] = (sm[1][0] + sm[1][1] + sm[1][2] + sm[1][3]) * invHW;
        qo[2] = (sm[2][0] + sm[2][1] + sm[2][2] + sm[2][3]) * invHW;
    }
}

// ---------------------------------------------------------------------------
// Kernel 4: out[b,k,Y,X] = sum_c x[b,c,Y,X] * q[b,k,c]
// float4 vectorized: each thread does 4 pixels, all 21 k. Write-bandwidth bound.
// grid (256, 8), block 256.
// ---------------------------------------------------------------------------
__global__ __launch_bounds__(256) void k_out(
    const float* __restrict__ x, float* __restrict__ out)
{
    __shared__ float sq[K_ * 3];
    int b = blockIdx.y;
    if (threadIdx.x < K_ * 3) sq[threadIdx.x] = g_q[(size_t)b * K_ * 3 + threadIdx.x];
    __syncthreads();

    int p4 = blockIdx.x * blockDim.x + threadIdx.x;     // float4 index, < 65536
    const float4* xb = (const float4*)(x + (size_t)b * 3 * PH);
    float4 x0 = xb[p4];
    float4 x1 = xb[(PH / 4) + p4];
    float4 x2 = xb[(PH / 2) + p4];

    float4* ob = (float4*)(out + (size_t)b * K_ * PH);
#pragma unroll
    for (int k = 0; k < K_; k++) {
        float w0 = sq[k * 3 + 0], w1 = sq[k * 3 + 1], w2 = sq[k * 3 + 2];
        float4 r;
        r.x = fmaf(x0.x, w0, fmaf(x1.x, w1, x2.x * w2));
        r.y = fmaf(x0.y, w0, fmaf(x1.y, w1, x2.y * w2));
        r.z = fmaf(x0.z, w0, fmaf(x1.z, w1, x2.z * w2));
        r.w = fmaf(x0.w, w0, fmaf(x1.w, w1, x2.w * w2));
        ob[(size_t)k * (PH / 4) + p4] = r;
    }
}

// ---------------------------------------------------------------------------
extern "C" void kernel_launch(void* const* d_in, const int* in_sizes, int n_in,
                              void* d_out, int out_size)
{
    const float* fm  = (const float*)d_in[0];  // [8,256,64,64]
    const float* x   = (const float*)d_in[1];  // [8,3,512,512]
    const float* Wc  = (const float*)d_in[2];  // [21,256]
    const float* bc  = (const float*)d_in[3];  // [21]
    float* out = (float*)d_out;                // [8,21,512,512]

    // 1. logits + softmax at 64x64
    {
        dim3 grid(PL / 128, B_);
        k_logits_softmax<<<grid, 128>>>(fm, Wc, bc);
    }
    // 2. adjoint bilinear downsample of x (separable)
    {
        int n = B_ * 3 * HH * HL;
        k_adj_x<<<(n + 255) / 256, 256>>>(x);
        int m = B_ * 3 * PL;
        k_adj_y<<<(m + 255) / 256, 256>>>();
    }
    // 3. q centroids
    k_q<<<B_ * K_, 128>>>();
    // 4. final output
    {
        dim3 grid((PH / 4) / 256, B_);
        k_out<<<grid, 256>>>(x, out);
    }
}

// round 2
// speedup vs baseline: 1.0645x; 1.0645x over previous
#include <cuda_runtime.h>
#include <cuda_bf16.h>

// Problem constants
#define B_  8
#define C_  256
#define K_  21
#define HL  64            // low-res H=W
#define PL  (HL*HL)       // 4096 low-res pixels
#define HH  512           // hi-res H=W
#define PH  (HH*HH)       // 262144 hi-res pixels
#define NBLK 32           // blocks per batch in fused kernel (PL/128)

// Scratch (device globals; no allocation allowed)
__device__ float g_tmpx [B_ * 3 * HH * HL];          // X-pass adjoint (3 MB)
__device__ float g_xdown[B_ * 3 * PL];               // adjoint-downsampled x
__device__ float g_part [B_ * NBLK * K_ * 3];        // q block partials
__device__ float g_q    [B_ * K_ * 3];               // color centroids

// ---------------------------------------------------------------------------
// Kernel 1: adjoint of bilinear upsample (align_corners), X direction.
// One 256-thread block handles 4 hires rows; row staged in smem (coalesced).
// tmpx[b,c,Y,xl] = sum_X w(X->xl) * x[b,c,Y,X]
// ---------------------------------------------------------------------------
__global__ __launch_bounds__(256) void k_adj_x(const float* __restrict__ x)
{
    __shared__ float srow[4][HH];
    int sub    = threadIdx.x >> 6;      // row slot 0..3
    int lane64 = threadIdx.x & 63;      // xl / load lane
    int rowid  = blockIdx.x * 4 + sub;  // (b*3+c)*HH + Y, total 12288

    // coalesced row load: 64 threads x 2 float4 = 512 floats
    {
        float4*       s4 = (float4*)srow[sub];
        const float4* r4 = (const float4*)(x + (size_t)rowid * HH);
        s4[lane64]      = r4[lane64];
        s4[64 + lane64] = r4[64 + lane64];
    }
    __syncthreads();

    const int   xl    = lane64;
    const float scale = 63.0f / 511.0f;
    int Xlo = max(0,      (int)floorf((xl - 1) * (511.0f / 63.0f)));
    int Xhi = min(HH - 1, (int)ceilf ((xl + 1) * (511.0f / 63.0f)));

    float s = 0.f;
    const float* row = srow[sub];
    for (int X = Xlo; X <= Xhi; X++) {
        float xs = (float)X * scale;
        int   x0 = (int)xs;                 // floor (xs >= 0)
        float wx = xs - (float)x0;
        int   x1 = min(x0 + 1, HL - 1);
        float w  = (x0 == xl ? (1.0f - wx) : 0.0f) + (x1 == xl ? wx : 0.0f);
        s = fmaf(w, row[X], s);
    }
    g_tmpx[(size_t)rowid * HL + xl] = s;
}

// ---------------------------------------------------------------------------
// Kernel 2: adjoint, Y direction: xdown[b,c,yl,xl] = sum_Y w(Y->yl)*tmpx[b,c,Y,xl]
// ---------------------------------------------------------------------------
__global__ void k_adj_y()
{
    int idx = blockIdx.x * blockDim.x + threadIdx.x;
    if (idx >= B_ * 3 * PL) return;
    int xl = idx & (HL - 1);
    int yl = (idx >> 6) & (HL - 1);
    int bc = idx >> 12;

    const float scale = 63.0f / 511.0f;
    int Ylo = max(0,      (int)floorf((yl - 1) * (511.0f / 63.0f)));
    int Yhi = min(HH - 1, (int)ceilf ((yl + 1) * (511.0f / 63.0f)));

    const float* col = g_tmpx + (size_t)bc * HH * HL + xl;
    float s = 0.f;
    for (int Y = Ylo; Y <= Yhi; Y++) {
        float ys = (float)Y * scale;
        int   y0 = (int)ys;
        float wy = ys - (float)y0;
        int   y1 = min(y0 + 1, HL - 1);
        float w  = (y0 == yl ? (1.0f - wy) : 0.0f) + (y1 == yl ? wy : 0.0f);
        s = fmaf(w, col[(size_t)Y * HL], s);
    }
    g_xdown[idx] = s;
}

// ---------------------------------------------------------------------------
// Kernel 3 (fused): logits -> softmax -> q block-partials. No seg materialized.
// grid (32, 8), block 128, one thread per low-res pixel.
// part[b,blk,k,c] = sum_{p in blk} softmax_k(p) * xdown[b,c,p]
// ---------------------------------------------------------------------------
__global__ __launch_bounds__(128) void k_fused(
    const float* __restrict__ fm, const float* __restrict__ Wc,
    const float* __restrict__ bc)
{
    __shared__ float4 sW4[K_][C_ / 4];      // 21.5 KB, W rows as float4
    __shared__ float  sb[K_];
    __shared__ float  spart[4][K_ * 3];     // per-warp partials

    int tid = threadIdx.x;
    for (int i = tid; i < K_ * C_ / 4; i += 128)
        ((float4*)sW4)[i] = ((const float4*)Wc)[i];
    if (tid < K_) sb[tid] = bc[tid];
    __syncthreads();

    int b = blockIdx.y;
    int p = blockIdx.x * 128 + tid;
    const float* fmb = fm + (size_t)b * C_ * PL + p;

    float acc[K_];
#pragma unroll
    for (int k = 0; k < K_; k++) acc[k] = sb[k];

#pragma unroll 2
    for (int c4 = 0; c4 < C_ / 4; c4++) {
        float v0 = fmb[(c4 * 4 + 0) * PL];
        float v1 = fmb[(c4 * 4 + 1) * PL];
        float v2 = fmb[(c4 * 4 + 2) * PL];
        float v3 = fmb[(c4 * 4 + 3) * PL];
#pragma unroll
        for (int k = 0; k < K_; k++) {
            float4 w = sW4[k][c4];
            float a = acc[k];
            a = fmaf(v0, w.x, a);
            a = fmaf(v1, w.y, a);
            a = fmaf(v2, w.z, a);
            a = fmaf(v3, w.w, a);
            acc[k] = a;
        }
    }

    // softmax over K in registers
    float m = acc[0];
#pragma unroll
    for (int k = 1; k < K_; k++) m = fmaxf(m, acc[k]);
    float s = 0.f;
#pragma unroll
    for (int k = 0; k < K_; k++) { acc[k] = __expf(acc[k] - m); s += acc[k]; }
    float inv = 1.0f / s;
#pragma unroll
    for (int k = 0; k < K_; k++) acc[k] *= inv;

    // q partial: need xdown for this pixel, 3 channels
    const float* xdb = g_xdown + (size_t)b * 3 * PL + p;
    float x0 = xdb[0], x1 = xdb[PL], x2 = xdb[2 * PL];

    int w = tid >> 5, l = tid & 31;
#pragma unroll
    for (int k = 0; k < K_; k++) {
        float v0 = acc[k] * x0, v1 = acc[k] * x1, v2 = acc[k] * x2;
#pragma unroll
        for (int off = 16; off > 0; off >>= 1) {
            v0 += __shfl_down_sync(0xffffffffu, v0, off);
            v1 += __shfl_down_sync(0xffffffffu, v1, off);
            v2 += __shfl_down_sync(0xffffffffu, v2, off);
        }
        if (l == 0) {
            spart[w][k * 3 + 0] = v0;
            spart[w][k * 3 + 1] = v1;
            spart[w][k * 3 + 2] = v2;
        }
    }
    __syncthreads();
    if (tid < K_ * 3) {
        float ps = spart[0][tid] + spart[1][tid] + spart[2][tid] + spart[3][tid];
        g_part[((size_t)b * NBLK + blockIdx.x) * (K_ * 3) + tid] = ps;
    }
}

// ---------------------------------------------------------------------------
// Kernel 4: reduce block partials -> q. 504 outputs.
// ---------------------------------------------------------------------------
__global__ void k_qred()
{
    int i = blockIdx.x * blockDim.x + threadIdx.x;   // b*63 + j
    if (i >= B_ * K_ * 3) return;
    int b = i / (K_ * 3), j = i % (K_ * 3);
    float s = 0.f;
#pragma unroll
    for (int blk = 0; blk < NBLK; blk++)
        s += g_part[((size_t)b * NBLK + blk) * (K_ * 3) + j];
    g_q[i] = s * (1.0f / (float)PH);
}

// ---------------------------------------------------------------------------
// Kernel 5: out[b,k,Y,X] = sum_c x[b,c,Y,X] * q[b,k,c]
// float4 vectorized; streaming stores (evict-first) for the 176 MB output.
// ---------------------------------------------------------------------------
__global__ __launch_bounds__(256) void k_out(
    const float* __restrict__ x, float* __restrict__ out)
{
    __shared__ float sq[K_ * 3];
    int b = blockIdx.y;
    if (threadIdx.x < K_ * 3) sq[threadIdx.x] = g_q[(size_t)b * K_ * 3 + threadIdx.x];
    __syncthreads();

    int p4 = blockIdx.x * blockDim.x + threadIdx.x;     // float4 index < 65536
    const float4* xb = (const float4*)(x + (size_t)b * 3 * PH);
    float4 x0 = xb[p4];
    float4 x1 = xb[(PH / 4) + p4];
    float4 x2 = xb[(PH / 2) + p4];

    float4* ob = (float4*)(out + (size_t)b * K_ * PH);
#pragma unroll
    for (int k = 0; k < K_; k++) {
        float w0 = sq[k * 3 + 0], w1 = sq[k * 3 + 1], w2 = sq[k * 3 + 2];
        float4 r;
        r.x = fmaf(x0.x, w0, fmaf(x1.x, w1, x2.x * w2));
        r.y = fmaf(x0.y, w0, fmaf(x1.y, w1, x2.y * w2));
        r.z = fmaf(x0.z, w0, fmaf(x1.z, w1, x2.z * w2));
        r.w = fmaf(x0.w, w0, fmaf(x1.w, w1, x2.w * w2));
        __stcs(&ob[(size_t)k * (PH / 4) + p4], r);
    }
}

// ---------------------------------------------------------------------------
extern "C" void kernel_launch(void* const* d_in, const int* in_sizes, int n_in,
                              void* d_out, int out_size)
{
    const float* fm  = (const float*)d_in[0];  // [8,256,64,64]
    const float* x   = (const float*)d_in[1];  // [8,3,512,512]
    const float* Wc  = (const float*)d_in[2];  // [21,256]
    const float* bc  = (const float*)d_in[3];  // [21]
    float* out = (float*)d_out;                // [8,21,512,512]

    // 1+2. adjoint bilinear downsample of x (separable)
    k_adj_x<<<B_ * 3 * HH / 4, 256>>>(x);
    {
        int m = B_ * 3 * PL;
        k_adj_y<<<(m + 255) / 256, 256>>>();
    }
    // 3. fused logits + softmax + q partials
    {
        dim3 grid(NBLK, B_);
        k_fused<<<grid, 128>>>(fm, Wc, bc);
    }
    // 4. q reduce
    k_qred<<<2, 256>>>();
    // 5. final output
    {
        dim3 grid((PH / 4) / 256, B_);
        k_out<<<grid, 256>>>(x, out);
    }
}

// round 5
// speedup vs baseline: 1.1321x; 1.0635x over previous
#include <cuda_runtime.h>
#include <cuda_bf16.h>

// Problem constants
#define B_  8
#define C_  256
#define K_  21
#define KP  24            // K padded to 12 f32x2 pairs
#define HL  64
#define PL  (HL*HL)       // 4096 low-res pixels
#define HH  512
#define PH  (HH*HH)       // 262144 hi-res pixels
#define NBLK 32           // q-partial blocks per batch

// Scratch (device globals)
__device__ float g_tmpx[B_ * 3 * HH * HL];       // X-pass adjoint (3 MB)
__device__ float g_part[B_ * NBLK * K_ * 3];     // q block partials

// packed f32x2 helpers
#define FMA2(acc, v2, w2) \
    asm("fma.rn.f32x2 %0, %1, %2, %0;" : "+l"(acc) : "l"(v2), "l"(w2))
__device__ __forceinline__ unsigned long long pack2(float lo, float hi) {
    unsigned long long r;
    asm("mov.b64 %0, {%1, %2};" : "=l"(r) : "r"(__float_as_uint(lo)), "r"(__float_as_uint(hi)));
    return r;
}
__device__ __forceinline__ void unpack2(unsigned long long v, float& lo, float& hi) {
    unsigned int a, b;
    asm("mov.b64 {%0, %1}, %2;" : "=r"(a), "=r"(b) : "l"(v));
    lo = __uint_as_float(a); hi = __uint_as_float(b);
}

// ---------------------------------------------------------------------------
// Kernel 1: adjoint of bilinear upsample (align_corners), X direction.
// One 256-thread block handles 4 hires rows; rows staged in smem.
// ---------------------------------------------------------------------------
__global__ __launch_bounds__(256) void k_adj_x(const float* __restrict__ x)
{
    __shared__ float srow[4][HH];
    int sub    = threadIdx.x >> 6;
    int lane64 = threadIdx.x & 63;
    int rowid  = blockIdx.x * 4 + sub;         // (b*3+c)*HH + Y

    {
        float4*       s4 = (float4*)srow[sub];
        const float4* r4 = (const float4*)(x + (size_t)rowid * HH);
        s4[lane64]      = r4[lane64];
        s4[64 + lane64] = r4[64 + lane64];
    }
    __syncthreads();

    const int   xl    = lane64;
    const float scale = 63.0f / 511.0f;
    int Xlo = max(0,      (int)floorf((xl - 1) * (511.0f / 63.0f)));
    int Xhi = min(HH - 1, (int)ceilf ((xl + 1) * (511.0f / 63.0f)));

    float s = 0.f;
    const float* row = srow[sub];
    for (int X = Xlo; X <= Xhi; X++) {
        float xs = (float)X * scale;
        int   x0 = (int)xs;
        float wx = xs - (float)x0;
        int   x1 = min(x0 + 1, HL - 1);
        float w  = (x0 == xl ? (1.0f - wx) : 0.0f) + (x1 == xl ? wx : 0.0f);
        s = fmaf(w, row[X], s);
    }
    g_tmpx[(size_t)rowid * HL + xl] = s;
}

// ---------------------------------------------------------------------------
// Kernel 2 (fused): Y-adjoint (in-register) + logits (f32x2 GEMM) + softmax
//                   + q block-partials.
// grid (32, 8), block 128, one thread per low-res pixel.
// ---------------------------------------------------------------------------
__global__ __launch_bounds__(128) void k_fused(
    const float* __restrict__ fm, const float* __restrict__ Wc,
    const float* __restrict__ bc)
{
    __shared__ ulonglong2 sWT2[C_][6];        // W^T padded: 24 floats/c (24.6 KB)
    __shared__ float      spart[4][K_ * 3];

    int tid = threadIdx.x;
    // fill W^T (padded with zeros for k >= 21); float view of sWT2 is [C_][KP]
    {
        float* sWTf = (float*)sWT2;
        for (int i = tid; i < C_ * KP; i += 128) {
            int c = i / KP, k = i % KP;
            sWTf[i] = (k < K_) ? Wc[k * C_ + c] : 0.0f;
        }
    }
    __syncthreads();

    int b = blockIdx.y;
    int p = blockIdx.x * 128 + tid;
    int xl = p & (HL - 1);
    int yl = p >> 6;

    // --- Y-adjoint gather: xdown[c] for this pixel, c=0..2 ---
    float xd0 = 0.f, xd1 = 0.f, xd2 = 0.f;
    {
        const float scale = 63.0f / 511.0f;
        int Ylo = max(0,      (int)floorf((yl - 1) * (511.0f / 63.0f)));
        int Yhi = min(HH - 1, (int)ceilf ((yl + 1) * (511.0f / 63.0f)));
        const float* t0 = g_tmpx + ((size_t)(b * 3 + 0) * HH) * HL + xl;
        const float* t1 = g_tmpx + ((size_t)(b * 3 + 1) * HH) * HL + xl;
        const float* t2 = g_tmpx + ((size_t)(b * 3 + 2) * HH) * HL + xl;
        for (int Y = Ylo; Y <= Yhi; Y++) {
            float ys = (float)Y * scale;
            int   y0 = (int)ys;
            float wy = ys - (float)y0;
            int   y1 = min(y0 + 1, HL - 1);
            float w  = (y0 == yl ? (1.0f - wy) : 0.0f) + (y1 == yl ? wy : 0.0f);
            size_t o = (size_t)Y * HL;
            xd0 = fmaf(w, t0[o], xd0);
            xd1 = fmaf(w, t1[o], xd1);
            xd2 = fmaf(w, t2[o], xd2);
        }
    }

    // --- logits GEMM, packed f32x2 over 12 k-pairs ---
    const float* fmb = fm + (size_t)b * C_ * PL + p;
    unsigned long long acc2[KP / 2];
#pragma unroll
    for (int j = 0; j < KP / 2; j++) {
        float blo = (2 * j     < K_) ? bc[2 * j]     : 0.0f;
        float bhi = (2 * j + 1 < K_) ? bc[2 * j + 1] : 0.0f;
        acc2[j] = pack2(blo, bhi);
    }

#pragma unroll 4
    for (int c = 0; c < C_; c++) {
        float v = fmb[(size_t)c * PL];
        unsigned long long v2 = pack2(v, v);
#pragma unroll
        for (int j = 0; j < 6; j++) {
            ulonglong2 w = sWT2[c][j];
            FMA2(acc2[2 * j],     v2, w.x);
            FMA2(acc2[2 * j + 1], v2, w.y);
        }
    }

    float acc[K_ + 1];
#pragma unroll
    for (int j = 0; j < (K_ + 1) / 2; j++)
        unpack2(acc2[j], acc[2 * j], acc[2 * j + 1]);

    // --- softmax over K ---
    float m = acc[0];
#pragma unroll
    for (int k = 1; k < K_; k++) m = fmaxf(m, acc[k]);
    float s = 0.f;
#pragma unroll
    for (int k = 0; k < K_; k++) { acc[k] = __expf(acc[k] - m); s += acc[k]; }
    float inv = 1.0f / s;

    // --- q partials ---
    int w = tid >> 5, l = tid & 31;
#pragma unroll
    for (int k = 0; k < K_; k++) {
        float sv = acc[k] * inv;
        float v0 = sv * xd0, v1 = sv * xd1, v2 = sv * xd2;
#pragma unroll
        for (int off = 16; off > 0; off >>= 1) {
            v0 += __shfl_down_sync(0xffffffffu, v0, off);
            v1 += __shfl_down_sync(0xffffffffu, v1, off);
            v2 += __shfl_down_sync(0xffffffffu, v2, off);
        }
        if (l == 0) {
            spart[w][k * 3 + 0] = v0;
            spart[w][k * 3 + 1] = v1;
            spart[w][k * 3 + 2] = v2;
        }
    }
    __syncthreads();
    if (tid < K_ * 3) {
        float ps = spart[0][tid] + spart[1][tid] + spart[2][tid] + spart[3][tid];
        g_part[((size_t)b * NBLK + blockIdx.x) * (K_ * 3) + tid] = ps;
    }
}

// ---------------------------------------------------------------------------
// Kernel 3: q reduce (in-block, redundant per block) + final output.
// out[b,k,Y,X] = sum_c x[b,c,Y,X] * q[b,k,c]; streaming stores.
// ---------------------------------------------------------------------------
__global__ __launch_bounds__(256) void k_out(
    const float* __restrict__ x, float* __restrict__ out)
{
    __shared__ float sq[K_ * 3];
    int b = blockIdx.y;
    if (threadIdx.x < K_ * 3) {
        const float* pp = g_part + (size_t)b * NBLK * (K_ * 3) + threadIdx.x;
        float s = 0.f;
#pragma unroll
        for (int blk = 0; blk < NBLK; blk++) s += pp[blk * (K_ * 3)];
        sq[threadIdx.x] = s * (1.0f / (float)PH);
    }
    __syncthreads();

    int p4 = blockIdx.x * blockDim.x + threadIdx.x;     // float4 index < 65536
    const float4* xb = (const float4*)(x + (size_t)b * 3 * PH);
    float4 x0 = xb[p4];
    float4 x1 = xb[(PH / 4) + p4];
    float4 x2 = xb[(PH / 2) + p4];

    float4* ob = (float4*)(out + (size_t)b * K_ * PH);
#pragma unroll
    for (int k = 0; k < K_; k++) {
        float w0 = sq[k * 3 + 0], w1 = sq[k * 3 + 1], w2 = sq[k * 3 + 2];
        float4 r;
        r.x = fmaf(x0.x, w0, fmaf(x1.x, w1, x2.x * w2));
        r.y = fmaf(x0.y, w0, fmaf(x1.y, w1, x2.y * w2));
        r.z = fmaf(x0.z, w0, fmaf(x1.z, w1, x2.z * w2));
        r.w = fmaf(x0.w, w0, fmaf(x1.w, w1, x2.w * w2));
        __stcs(&ob[(size_t)k * (PH / 4) + p4], r);
    }
}

// ---------------------------------------------------------------------------
extern "C" void kernel_launch(void* const* d_in, const int* in_sizes, int n_in,
                              void* d_out, int out_size)
{
    const float* fm  = (const float*)d_in[0];  // [8,256,64,64]
    const float* x   = (const float*)d_in[1];  // [8,3,512,512]
    const float* Wc  = (const float*)d_in[2];  // [21,256]
    const float* bc  = (const float*)d_in[3];  // [21]
    float* out = (float*)d_out;                // [8,21,512,512]

    k_adj_x<<<B_ * 3 * HH / 4, 256>>>(x);
    {
        dim3 grid(NBLK, B_);
        k_fused<<<grid, 128>>>(fm, Wc, bc);
    }
    {
        dim3 grid((PH / 4) / 256, B_);
        k_out<<<grid, 256>>>(x, out);
    }
}